// round 8
// baseline (speedup 1.0000x reference)
#include <cuda_runtime.h>
#include <stdint.h>

#define N_NODES 50000
#define N_PAD   50048   // multiple of 128 for k_h2 tiling
#define N_EDGES 800000
#define HID     128
#define OUTC    64

// ---- scratch (device globals, zero-initialized at module load; k_gather2
//      re-zeroes g_deg/g_total at the end of every call so each replay
//      starts from the same state; no allocation anywhere) ----
__device__ int   g_deg[N_NODES];
__device__ int   g_rowstart[N_NODES];
__device__ int   g_rank[N_EDGES];
__device__ int   g_csrc[N_EDGES];
__device__ int   g_total;
__device__ float g_dinv[N_NODES];
__device__ __align__(16) float g_v[N_PAD * 4];      // layer-1 aggregated 3-vec (pad stays 0)
__device__ __align__(16) float g_h2[N_PAD * OUTC];

#define PACK2(d, lo, hi) asm("mov.b64 %0, {%1, %2};" : "=l"(d) : "f"(lo), "f"(hi))
#define UNPACK2(lo, hi, s) asm("mov.b64 {%0, %1}, %2;" : "=f"(lo), "=f"(hi) : "l"(s))
#define FMA2(d, a, b, c) asm("fma.rn.f32x2 %0, %1, %2, %3;" : "=l"(d) : "l"(a), "l"(b), "l"(c))

// 1) degree histogram on dst + per-edge rank (the atomic return IS the rank).
//    Rank store is coalesced. 2 edges/thread keeps grid/occupancy high.
__global__ void k_degrank(const int* __restrict__ ei) {
    int t = blockIdx.x * blockDim.x + threadIdx.x;
    if (t >= N_EDGES / 2) return;
    int2 d = ((const int2*)(ei + N_EDGES))[t];
    int r0 = atomicAdd(&g_deg[d.x], 1);
    int r1 = atomicAdd(&g_deg[d.y], 1);
    ((int2*)g_rank)[t] = make_int2(r0, r1);
}

// 2) row allocation: warp-shuffle scan + one atomic per warp (order-free rows)
__global__ void k_assign() {
    int i = blockIdx.x * blockDim.x + threadIdx.x;
    int lane = threadIdx.x & 31;
    int deg = (i < N_NODES) ? g_deg[i] : 0;
    int incl = deg;
    #pragma unroll
    for (int o = 1; o < 32; o <<= 1) {
        int v = __shfl_up_sync(0xffffffff, incl, o);
        if (lane >= o) incl += v;
    }
    int base = 0;
    if (lane == 31) base = atomicAdd(&g_total, incl);   // incl@31 = warp total
    base = __shfl_sync(0xffffffff, base, 31);
    if (i < N_NODES) {
        g_rowstart[i] = base + incl - deg;
        g_dinv[i] = rsqrtf((float)(deg + 1));
    }
}

// 3) CSR scatter — ATOMIC-FREE: pos = rowstart[dst] + rank[e]. 4 edges/thread.
__global__ void k_csr(const int* __restrict__ ei) {
    int t = blockIdx.x * blockDim.x + threadIdx.x;
    if (t >= N_EDGES / 4) return;
    int4 s = ((const int4*)ei)[t];
    int4 d = ((const int4*)(ei + N_EDGES))[t];
    int4 r = ((const int4*)g_rank)[t];
    int b0 = g_rowstart[d.x];
    int b1 = g_rowstart[d.y];
    int b2 = g_rowstart[d.z];
    int b3 = g_rowstart[d.w];
    g_csrc[b0 + r.x] = s.x;
    g_csrc[b1 + r.y] = s.y;
    g_csrc[b2 + r.z] = s.z;
    g_csrc[b3 + r.w] = s.w;
}

// 4) layer-1 gather in 3-dim space: warp per node, atomic-free
__global__ void k_gather1(const float* __restrict__ x) {
    int gid = blockIdx.x * blockDim.x + threadIdx.x;
    int node = gid >> 5;
    int lane = gid & 31;
    if (node >= N_NODES) return;
    int row = g_rowstart[node];
    int end = row + g_deg[node];
    float a0 = 0.f, a1 = 0.f, a2 = 0.f;
    for (int e = row + lane; e < end; e += 32) {
        int s = g_csrc[e];
        float w = g_dinv[s];
        a0 = fmaf(__ldg(&x[s * 3 + 0]), w, a0);
        a1 = fmaf(__ldg(&x[s * 3 + 1]), w, a1);
        a2 = fmaf(__ldg(&x[s * 3 + 2]), w, a2);
    }
    #pragma unroll
    for (int o = 16; o > 0; o >>= 1) {
        a0 += __shfl_down_sync(0xffffffff, a0, o);
        a1 += __shfl_down_sync(0xffffffff, a1, o);
        a2 += __shfl_down_sync(0xffffffff, a2, o);
    }
    if (lane == 0) {
        float dd = g_dinv[node];
        float sl = dd * dd;
        float4 v;
        v.x = fmaf(dd, a0, sl * __ldg(&x[node * 3 + 0]));
        v.y = fmaf(dd, a1, sl * __ldg(&x[node * 3 + 1]));
        v.z = fmaf(dd, a2, sl * __ldg(&x[node * 3 + 2]));
        v.w = 0.f;
        ((float4*)g_v)[node] = v;
    }
}

// 5) fused h1 (relu(v@W1+b1), smem k-major) + h2 = h1 @ W2 with fma.rn.f32x2
//    128 nodes/block, 256 threads; thread = (8 nodes = 4 node-pairs, 4 cols).
__global__ void __launch_bounds__(256) k_h2(const float* __restrict__ W1,
                                            const float* __restrict__ b1,
                                            const float* __restrict__ W2) {
    __shared__ float4 sW2[HID * 16];    // [k][16 col-quads]       32 KB
    __shared__ float  sh1T[HID * 128];  // [k][node] transposed    64 KB
    int tid = threadIdx.x;
    int nodeBase = blockIdx.x * 128;

    #pragma unroll 4
    for (int i = tid; i < HID * 16; i += 256) sW2[i] = ((const float4*)W2)[i];

    #pragma unroll 4
    for (int i = tid; i < 128 * 32; i += 256) {
        int node = i & 127;
        int q    = i >> 7;
        float4 v  = ((const float4*)g_v)[nodeBase + node];
        float4 w0 = __ldg(&((const float4*)W1)[0 * 32 + q]);
        float4 w1 = __ldg(&((const float4*)W1)[1 * 32 + q]);
        float4 w2 = __ldg(&((const float4*)W1)[2 * 32 + q]);
        float4 bq = __ldg(&((const float4*)b1)[q]);
        sh1T[(4 * q + 0) * 128 + node] = fmaxf(fmaf(v.x, w0.x, fmaf(v.y, w1.x, fmaf(v.z, w2.x, bq.x))), 0.f);
        sh1T[(4 * q + 1) * 128 + node] = fmaxf(fmaf(v.x, w0.y, fmaf(v.y, w1.y, fmaf(v.z, w2.y, bq.y))), 0.f);
        sh1T[(4 * q + 2) * 128 + node] = fmaxf(fmaf(v.x, w0.z, fmaf(v.y, w1.z, fmaf(v.z, w2.z, bq.z))), 0.f);
        sh1T[(4 * q + 3) * 128 + node] = fmaxf(fmaf(v.x, w0.w, fmaf(v.y, w1.w, fmaf(v.z, w2.w, bq.w))), 0.f);
    }
    __syncthreads();

    int c  = tid & 15;        // cols 4c..4c+3
    int m0 = (tid >> 4) * 8;  // nodes m0..m0+7 (4 packed pairs)

    unsigned long long acc[4][4];
    #pragma unroll
    for (int p = 0; p < 4; p++)
        #pragma unroll
        for (int cc = 0; cc < 4; cc++) acc[p][cc] = 0ull;

    #pragma unroll 2
    for (int kb = 0; kb < HID; kb += 4) {
        #pragma unroll
        for (int kk = 0; kk < 4; kk++) {
            int k = kb + kk;
            float4 w = sW2[k * 16 + c];
            unsigned long long wp[4];
            PACK2(wp[0], w.x, w.x);
            PACK2(wp[1], w.y, w.y);
            PACK2(wp[2], w.z, w.z);
            PACK2(wp[3], w.w, w.w);
            float4 ha = *(const float4*)&sh1T[k * 128 + m0];
            float4 hb = *(const float4*)&sh1T[k * 128 + m0 + 4];
            unsigned long long hp[4];
            PACK2(hp[0], ha.x, ha.y);
            PACK2(hp[1], ha.z, ha.w);
            PACK2(hp[2], hb.x, hb.y);
            PACK2(hp[3], hb.z, hb.w);
            #pragma unroll
            for (int p = 0; p < 4; p++) {
                FMA2(acc[p][0], hp[p], wp[0], acc[p][0]);
                FMA2(acc[p][1], hp[p], wp[1], acc[p][1]);
                FMA2(acc[p][2], hp[p], wp[2], acc[p][2]);
                FMA2(acc[p][3], hp[p], wp[3], acc[p][3]);
            }
        }
    }

    #pragma unroll
    for (int p = 0; p < 4; p++) {
        float4 r0, r1;
        UNPACK2(r0.x, r1.x, acc[p][0]);
        UNPACK2(r0.y, r1.y, acc[p][1]);
        UNPACK2(r0.z, r1.z, acc[p][2]);
        UNPACK2(r0.w, r1.w, acc[p][3]);
        int n0 = nodeBase + m0 + 2 * p;
        ((float4*)g_h2)[(size_t)n0 * 16 + c] = r0;
        ((float4*)g_h2)[(size_t)(n0 + 1) * 16 + c] = r1;
    }
}

// 6) layer-2 gather, 16 threads/node, unroll x4; also resets g_deg/g_total
//    for the next replay (safe: a node's 16 lanes read deg in lockstep
//    before the q==0 lane zeroes it).
__global__ void k_gather2(const float* __restrict__ b2,
                          float* __restrict__ out) {
    int gid = blockIdx.x * blockDim.x + threadIdx.x;
    int node = gid >> 4;
    int q    = gid & 15;
    if (node >= N_NODES) return;
    int row = g_rowstart[node];
    int deg = g_deg[node];
    int end = row + deg;
    if (q == 0) g_deg[node] = 0;     // reset for next call
    if (gid == 0) g_total = 0;
    float4 acc = make_float4(0.f, 0.f, 0.f, 0.f);
    int e = row;
    for (; e + 4 <= end; e += 4) {
        int s0 = g_csrc[e];
        int s1 = g_csrc[e + 1];
        int s2 = g_csrc[e + 2];
        int s3 = g_csrc[e + 3];
        float w0 = g_dinv[s0];
        float w1 = g_dinv[s1];
        float w2 = g_dinv[s2];
        float w3 = g_dinv[s3];
        float4 h0 = ((const float4*)g_h2)[(size_t)s0 * 16 + q];
        float4 h1 = ((const float4*)g_h2)[(size_t)s1 * 16 + q];
        float4 h2 = ((const float4*)g_h2)[(size_t)s2 * 16 + q];
        float4 h3 = ((const float4*)g_h2)[(size_t)s3 * 16 + q];
        acc.x = fmaf(w0, h0.x, fmaf(w1, h1.x, fmaf(w2, h2.x, fmaf(w3, h3.x, acc.x))));
        acc.y = fmaf(w0, h0.y, fmaf(w1, h1.y, fmaf(w2, h2.y, fmaf(w3, h3.y, acc.y))));
        acc.z = fmaf(w0, h0.z, fmaf(w1, h1.z, fmaf(w2, h2.z, fmaf(w3, h3.z, acc.z))));
        acc.w = fmaf(w0, h0.w, fmaf(w1, h1.w, fmaf(w2, h2.w, fmaf(w3, h3.w, acc.w))));
    }
    for (; e < end; e++) {
        int s = g_csrc[e];
        float w = g_dinv[s];
        float4 h = ((const float4*)g_h2)[(size_t)s * 16 + q];
        acc.x = fmaf(w, h.x, acc.x);
        acc.y = fmaf(w, h.y, acc.y);
        acc.z = fmaf(w, h.z, acc.z);
        acc.w = fmaf(w, h.w, acc.w);
    }
    float dd = g_dinv[node];
    float sl = dd * dd;
    float4 hs = ((const float4*)g_h2)[(size_t)node * 16 + q];
    float4 bb = __ldg(&((const float4*)b2)[q]);
    float4 o;
    o.x = fmaf(dd, acc.x, fmaf(sl, hs.x, bb.x));
    o.y = fmaf(dd, acc.y, fmaf(sl, hs.y, bb.y));
    o.z = fmaf(dd, acc.z, fmaf(sl, hs.z, bb.z));
    o.w = fmaf(dd, acc.w, fmaf(sl, hs.w, bb.w));
    ((float4*)out)[(size_t)node * 16 + q] = o;
}

extern "C" void kernel_launch(void* const* d_in, const int* in_sizes, int n_in,
                              void* d_out, int out_size) {
    const float* x  = (const float*)d_in[0];
    const int*   ei = (const int*)d_in[1];   // int64 in ref -> int32 on device (JAX x64 off)
    const float* W1 = (const float*)d_in[2];
    const float* b1 = (const float*)d_in[3];
    const float* W2 = (const float*)d_in[4];
    const float* b2 = (const float*)d_in[5];
    float* out = (float*)d_out;

    k_degrank<<<(N_EDGES / 2 + 255) / 256, 256>>>(ei);
    k_assign<<<(N_NODES + 255) / 256, 256>>>();
    k_csr<<<(N_EDGES / 4 + 255) / 256, 256>>>(ei);
    k_gather1<<<(N_NODES * 32 + 255) / 256, 256>>>(x);
    k_h2<<<N_PAD / 128, 256>>>(W1, b1, W2);
    k_gather2<<<(N_NODES * 16 + 255) / 256, 256>>>(b2, out);
}

// round 9
// speedup vs baseline: 1.0457x; 1.0457x over previous
#include <cuda_runtime.h>
#include <stdint.h>

#define N_NODES 50000
#define N_PAD   50048   // multiple of 128 for k_h2 tiling
#define N_EDGES 800000
#define HID     128
#define OUTC    64

// ---- scratch (device globals, zero-initialized at module load; k_gather2
//      re-zeroes g_deg/g_total each call so every replay starts clean) ----
__device__ int   g_deg[N_NODES];
__device__ int   g_rowstart[N_NODES];
__device__ int   g_wpos[N_NODES];
__device__ int   g_csrc[N_EDGES];
__device__ int   g_total;
__device__ float g_dinv[N_PAD];                      // pad stays 0
__device__ __align__(16) float g_xw[N_NODES * 4];    // x * dinv, packed float4
__device__ __align__(16) float g_v[N_PAD * 4];       // layer-1 result (pad stays 0)
__device__ __align__(16) float g_h2w[N_PAD * OUTC];  // h2 * dinv

#define PACK2(d, lo, hi) asm("mov.b64 %0, {%1, %2};" : "=l"(d) : "f"(lo), "f"(hi))
#define UNPACK2(lo, hi, s) asm("mov.b64 {%0, %1}, %2;" : "=f"(lo), "=f"(hi) : "l"(s))
#define FMA2(d, a, b, c) asm("fma.rn.f32x2 %0, %1, %2, %3;" : "=l"(d) : "l"(a), "l"(b), "l"(c))

// 1) degree histogram on dst (REDG, no return); 2 edges/thread
__global__ void k_deg(const int* __restrict__ ei) {
    int t = blockIdx.x * blockDim.x + threadIdx.x;
    if (t >= N_EDGES / 2) return;
    int2 d = ((const int2*)(ei + N_EDGES))[t];
    atomicAdd(&g_deg[d.x], 1);
    atomicAdd(&g_deg[d.y], 1);
}

// 2) row allocation (warp scan + 1 atomic/warp) + dinv + premultiplied xw
__global__ void k_assign(const float* __restrict__ x) {
    int i = blockIdx.x * blockDim.x + threadIdx.x;
    int lane = threadIdx.x & 31;
    int deg = (i < N_NODES) ? g_deg[i] : 0;
    int incl = deg;
    #pragma unroll
    for (int o = 1; o < 32; o <<= 1) {
        int v = __shfl_up_sync(0xffffffff, incl, o);
        if (lane >= o) incl += v;
    }
    int base = 0;
    if (lane == 31) base = atomicAdd(&g_total, incl);   // incl@31 = warp total
    base = __shfl_sync(0xffffffff, base, 31);
    if (i < N_NODES) {
        g_rowstart[i] = base + incl - deg;
        g_wpos[i] = base + incl - deg;
        float dd = rsqrtf((float)(deg + 1));
        g_dinv[i] = dd;
        float4 xw;
        xw.x = __ldg(&x[i * 3 + 0]) * dd;
        xw.y = __ldg(&x[i * 3 + 1]) * dd;
        xw.z = __ldg(&x[i * 3 + 2]) * dd;
        xw.w = 0.f;
        ((float4*)g_xw)[i] = xw;
    }
}

// 3) CSR scatter: src indices grouped by dst; 2 edges/thread (best measured)
__global__ void k_csr(const int* __restrict__ ei) {
    int t = blockIdx.x * blockDim.x + threadIdx.x;
    if (t >= N_EDGES / 2) return;
    int2 s = ((const int2*)ei)[t];
    int2 d = ((const int2*)(ei + N_EDGES))[t];
    int p0 = atomicAdd(&g_wpos[d.x], 1);
    g_csrc[p0] = s.x;
    int p1 = atomicAdd(&g_wpos[d.y], 1);
    g_csrc[p1] = s.y;
}

// 4) layer-1 gather: THREAD per node; v[d] = dinv[d]*(sum xw[s] + xw[d]).
//    Per edge: 1 csrc load + 1 float4 load. Unroll x4 for MLP.
__global__ void k_gather1() {
    int node = blockIdx.x * blockDim.x + threadIdx.x;
    if (node >= N_NODES) return;
    int row = g_rowstart[node];
    int end = row + g_deg[node];
    float4 a = ((const float4*)g_xw)[node];   // self term (xw[d])
    int e = row;
    for (; e + 4 <= end; e += 4) {
        int s0 = g_csrc[e];
        int s1 = g_csrc[e + 1];
        int s2 = g_csrc[e + 2];
        int s3 = g_csrc[e + 3];
        float4 v0 = ((const float4*)g_xw)[s0];
        float4 v1 = ((const float4*)g_xw)[s1];
        float4 v2 = ((const float4*)g_xw)[s2];
        float4 v3 = ((const float4*)g_xw)[s3];
        a.x += (v0.x + v1.x) + (v2.x + v3.x);
        a.y += (v0.y + v1.y) + (v2.y + v3.y);
        a.z += (v0.z + v1.z) + (v2.z + v3.z);
    }
    for (; e < end; e++) {
        float4 v0 = ((const float4*)g_xw)[g_csrc[e]];
        a.x += v0.x;
        a.y += v0.y;
        a.z += v0.z;
    }
    float dd = g_dinv[node];
    ((float4*)g_v)[node] = make_float4(a.x * dd, a.y * dd, a.z * dd, 0.f);
}

// 5) fused h1 (relu(v@W1+b1), smem k-major) + h2 = h1 @ W2 via fma.rn.f32x2;
//    epilogue stores h2w = h2 * dinv[node].
__global__ void __launch_bounds__(256) k_h2(const float* __restrict__ W1,
                                            const float* __restrict__ b1,
                                            const float* __restrict__ W2) {
    __shared__ float4 sW2[HID * 16];    // 32 KB
    __shared__ float  sh1T[HID * 128];  // 64 KB, [k][node]
    int tid = threadIdx.x;
    int nodeBase = blockIdx.x * 128;

    #pragma unroll 4
    for (int i = tid; i < HID * 16; i += 256) sW2[i] = ((const float4*)W2)[i];

    #pragma unroll 4
    for (int i = tid; i < 128 * 32; i += 256) {
        int node = i & 127;
        int q    = i >> 7;
        float4 v  = ((const float4*)g_v)[nodeBase + node];
        float4 w0 = __ldg(&((const float4*)W1)[0 * 32 + q]);
        float4 w1 = __ldg(&((const float4*)W1)[1 * 32 + q]);
        float4 w2 = __ldg(&((const float4*)W1)[2 * 32 + q]);
        float4 bq = __ldg(&((const float4*)b1)[q]);
        sh1T[(4 * q + 0) * 128 + node] = fmaxf(fmaf(v.x, w0.x, fmaf(v.y, w1.x, fmaf(v.z, w2.x, bq.x))), 0.f);
        sh1T[(4 * q + 1) * 128 + node] = fmaxf(fmaf(v.x, w0.y, fmaf(v.y, w1.y, fmaf(v.z, w2.y, bq.y))), 0.f);
        sh1T[(4 * q + 2) * 128 + node] = fmaxf(fmaf(v.x, w0.z, fmaf(v.y, w1.z, fmaf(v.z, w2.z, bq.z))), 0.f);
        sh1T[(4 * q + 3) * 128 + node] = fmaxf(fmaf(v.x, w0.w, fmaf(v.y, w1.w, fmaf(v.z, w2.w, bq.w))), 0.f);
    }
    __syncthreads();

    int c  = tid & 15;        // cols 4c..4c+3
    int m0 = (tid >> 4) * 8;  // nodes m0..m0+7 (4 packed pairs)

    unsigned long long acc[4][4];
    #pragma unroll
    for (int p = 0; p < 4; p++)
        #pragma unroll
        for (int cc = 0; cc < 4; cc++) acc[p][cc] = 0ull;

    #pragma unroll 2
    for (int kb = 0; kb < HID; kb += 4) {
        #pragma unroll
        for (int kk = 0; kk < 4; kk++) {
            int k = kb + kk;
            float4 w = sW2[k * 16 + c];
            unsigned long long wp[4];
            PACK2(wp[0], w.x, w.x);
            PACK2(wp[1], w.y, w.y);
            PACK2(wp[2], w.z, w.z);
            PACK2(wp[3], w.w, w.w);
            float4 ha = *(const float4*)&sh1T[k * 128 + m0];
            float4 hb = *(const float4*)&sh1T[k * 128 + m0 + 4];
            unsigned long long hp[4];
            PACK2(hp[0], ha.x, ha.y);
            PACK2(hp[1], ha.z, ha.w);
            PACK2(hp[2], hb.x, hb.y);
            PACK2(hp[3], hb.z, hb.w);
            #pragma unroll
            for (int p = 0; p < 4; p++) {
                FMA2(acc[p][0], hp[p], wp[0], acc[p][0]);
                FMA2(acc[p][1], hp[p], wp[1], acc[p][1]);
                FMA2(acc[p][2], hp[p], wp[2], acc[p][2]);
                FMA2(acc[p][3], hp[p], wp[3], acc[p][3]);
            }
        }
    }

    #pragma unroll
    for (int p = 0; p < 4; p++) {
        int n0 = nodeBase + m0 + 2 * p;
        float d0 = g_dinv[n0];
        float d1 = g_dinv[n0 + 1];
        float4 r0, r1;
        UNPACK2(r0.x, r1.x, acc[p][0]);
        UNPACK2(r0.y, r1.y, acc[p][1]);
        UNPACK2(r0.z, r1.z, acc[p][2]);
        UNPACK2(r0.w, r1.w, acc[p][3]);
        r0.x *= d0; r0.y *= d0; r0.z *= d0; r0.w *= d0;
        r1.x *= d1; r1.y *= d1; r1.z *= d1; r1.w *= d1;
        ((float4*)g_h2w)[(size_t)n0 * 16 + c] = r0;
        ((float4*)g_h2w)[(size_t)(n0 + 1) * 16 + c] = r1;
    }
}

// 6) layer-2 gather, 16 threads/node (one float4 quad each), unroll x4.
//    out = dinv[d]*(sum h2w[s] + h2w[d]) + b2. Also resets deg/total.
__global__ void k_gather2(const float* __restrict__ b2,
                          float* __restrict__ out) {
    int gid = blockIdx.x * blockDim.x + threadIdx.x;
    int node = gid >> 4;
    int q    = gid & 15;
    if (node >= N_NODES) return;
    int row = g_rowstart[node];
    int deg = g_deg[node];
    int end = row + deg;
    if (q == 0) g_deg[node] = 0;     // reset for next call (lanes read deg above)
    if (gid == 0) g_total = 0;
    float4 acc = ((const float4*)g_h2w)[(size_t)node * 16 + q];  // self term
    int e = row;
    for (; e + 4 <= end; e += 4) {
        int s0 = g_csrc[e];
        int s1 = g_csrc[e + 1];
        int s2 = g_csrc[e + 2];
        int s3 = g_csrc[e + 3];
        float4 h0 = ((const float4*)g_h2w)[(size_t)s0 * 16 + q];
        float4 h1 = ((const float4*)g_h2w)[(size_t)s1 * 16 + q];
        float4 h2 = ((const float4*)g_h2w)[(size_t)s2 * 16 + q];
        float4 h3 = ((const float4*)g_h2w)[(size_t)s3 * 16 + q];
        acc.x += (h0.x + h1.x) + (h2.x + h3.x);
        acc.y += (h0.y + h1.y) + (h2.y + h3.y);
        acc.z += (h0.z + h1.z) + (h2.z + h3.z);
        acc.w += (h0.w + h1.w) + (h2.w + h3.w);
    }
    for (; e < end; e++) {
        float4 h = ((const float4*)g_h2w)[(size_t)g_csrc[e] * 16 + q];
        acc.x += h.x;
        acc.y += h.y;
        acc.z += h.z;
        acc.w += h.w;
    }
    float dd = g_dinv[node];
    float4 bb = __ldg(&((const float4*)b2)[q]);
    float4 o;
    o.x = fmaf(dd, acc.x, bb.x);
    o.y = fmaf(dd, acc.y, bb.y);
    o.z = fmaf(dd, acc.z, bb.z);
    o.w = fmaf(dd, acc.w, bb.w);
    ((float4*)out)[(size_t)node * 16 + q] = o;
}

extern "C" void kernel_launch(void* const* d_in, const int* in_sizes, int n_in,
                              void* d_out, int out_size) {
    const float* x  = (const float*)d_in[0];
    const int*   ei = (const int*)d_in[1];   // int64 in ref -> int32 on device (JAX x64 off)
    const float* W1 = (const float*)d_in[2];
    const float* b1 = (const float*)d_in[3];
    const float* W2 = (const float*)d_in[4];
    const float* b2 = (const float*)d_in[5];
    float* out = (float*)d_out;

    k_deg<<<(N_EDGES / 2 + 255) / 256, 256>>>(ei);
    k_assign<<<(N_NODES + 255) / 256, 256>>>(x);
    k_csr<<<(N_EDGES / 2 + 255) / 256, 256>>>(ei);
    k_gather1<<<(N_NODES + 255) / 256, 256>>>();
    k_h2<<<N_PAD / 128, 256>>>(W1, b1, W2);
    k_gather2<<<(N_NODES * 16 + 255) / 256, 256>>>(b2, out);
}

// round 10
// speedup vs baseline: 1.0791x; 1.0320x over previous
#include <cuda_runtime.h>
#include <stdint.h>

#define N_NODES 50000
#define N_PAD   50048   // multiple of 128 for k_h2 tiling
#define N_EDGES 800000
#define HID     128
#define OUTC    64

// ---- scratch (device globals, zero-initialized at module load; k_gather2
//      re-zeroes g_deg/g_total each call so every replay starts clean) ----
__device__ int   g_deg[N_NODES];
__device__ int   g_rowstart[N_NODES];
__device__ int   g_wpos[N_NODES];
__device__ int   g_csrc[N_EDGES];
__device__ int   g_total;
__device__ float g_dinv[N_PAD];                      // pad stays 0
__device__ __align__(16) float g_xw[N_NODES * 4];    // x * dinv, packed float4
__device__ __align__(16) float g_v[N_PAD * 4];       // layer-1 result (pad stays 0)
__device__ __align__(16) float g_h2w[N_PAD * OUTC];  // h2 * dinv

#define PACK2(d, lo, hi) asm("mov.b64 %0, {%1, %2};" : "=l"(d) : "f"(lo), "f"(hi))
#define UNPACK2(lo, hi, s) asm("mov.b64 {%0, %1}, %2;" : "=f"(lo), "=f"(hi) : "l"(s))
#define FMA2(d, a, b, c) asm("fma.rn.f32x2 %0, %1, %2, %3;" : "=l"(d) : "l"(a), "l"(b), "l"(c))

// 1) degree histogram on dst (REDG, no return); 2 edges/thread (best measured)
__global__ void k_deg(const int* __restrict__ ei) {
    int t = blockIdx.x * blockDim.x + threadIdx.x;
    if (t >= N_EDGES / 2) return;
    int2 d = ((const int2*)(ei + N_EDGES))[t];
    atomicAdd(&g_deg[d.x], 1);
    atomicAdd(&g_deg[d.y], 1);
}

// 2) row allocation (warp scan + 1 atomic/warp) + dinv + premultiplied xw
__global__ void k_assign(const float* __restrict__ x) {
    int i = blockIdx.x * blockDim.x + threadIdx.x;
    int lane = threadIdx.x & 31;
    int deg = (i < N_NODES) ? g_deg[i] : 0;
    int incl = deg;
    #pragma unroll
    for (int o = 1; o < 32; o <<= 1) {
        int v = __shfl_up_sync(0xffffffff, incl, o);
        if (lane >= o) incl += v;
    }
    int base = 0;
    if (lane == 31) base = atomicAdd(&g_total, incl);   // incl@31 = warp total
    base = __shfl_sync(0xffffffff, base, 31);
    if (i < N_NODES) {
        int rs = base + incl - deg;
        g_rowstart[i] = rs;
        g_wpos[i] = rs;
        float dd = rsqrtf((float)(deg + 1));
        g_dinv[i] = dd;
        float4 xw;
        xw.x = __ldg(&x[i * 3 + 0]) * dd;
        xw.y = __ldg(&x[i * 3 + 1]) * dd;
        xw.z = __ldg(&x[i * 3 + 2]) * dd;
        xw.w = 0.f;
        ((float4*)g_xw)[i] = xw;
    }
}

// 3) CSR scatter: src indices grouped by dst; 2 edges/thread (best measured)
__global__ void k_csr(const int* __restrict__ ei) {
    int t = blockIdx.x * blockDim.x + threadIdx.x;
    if (t >= N_EDGES / 2) return;
    int2 s = ((const int2*)ei)[t];
    int2 d = ((const int2*)(ei + N_EDGES))[t];
    int p0 = atomicAdd(&g_wpos[d.x], 1);
    g_csrc[p0] = s.x;
    int p1 = atomicAdd(&g_wpos[d.y], 1);
    g_csrc[p1] = s.y;
}

// 4) layer-1 gather: 8 threads/node, xw premultiplied.
//    v[d] = dinv[d]*(sum xw[s] + xw[d]). 3 segment-shfl rounds to reduce.
__global__ void k_gather1() {
    int gid = blockIdx.x * blockDim.x + threadIdx.x;
    int node = gid >> 3;
    int t8   = gid & 7;
    if (node >= N_NODES) return;
    int row = g_rowstart[node];
    int end = row + g_deg[node];
    float a0 = 0.f, a1 = 0.f, a2 = 0.f;
    for (int e = row + t8; e < end; e += 8) {
        float4 v = ((const float4*)g_xw)[g_csrc[e]];
        a0 += v.x;
        a1 += v.y;
        a2 += v.z;
    }
    #pragma unroll
    for (int o = 4; o > 0; o >>= 1) {   // reduce within 8-lane segment
        a0 += __shfl_down_sync(0xffffffff, a0, o, 8);
        a1 += __shfl_down_sync(0xffffffff, a1, o, 8);
        a2 += __shfl_down_sync(0xffffffff, a2, o, 8);
    }
    if (t8 == 0) {
        float4 self = ((const float4*)g_xw)[node];
        float dd = g_dinv[node];
        ((float4*)g_v)[node] = make_float4((a0 + self.x) * dd,
                                           (a1 + self.y) * dd,
                                           (a2 + self.z) * dd, 0.f);
    }
}

// 5) fused h1 (relu(v@W1+b1), smem k-major) + h2 = h1 @ W2 via fma.rn.f32x2;
//    epilogue stores h2w = h2 * dinv[node].
__global__ void __launch_bounds__(256) k_h2(const float* __restrict__ W1,
                                            const float* __restrict__ b1,
                                            const float* __restrict__ W2) {
    __shared__ float4 sW2[HID * 16];    // 32 KB
    __shared__ float  sh1T[HID * 128];  // 64 KB, [k][node]
    int tid = threadIdx.x;
    int nodeBase = blockIdx.x * 128;

    #pragma unroll 4
    for (int i = tid; i < HID * 16; i += 256) sW2[i] = ((const float4*)W2)[i];

    #pragma unroll 4
    for (int i = tid; i < 128 * 32; i += 256) {
        int node = i & 127;
        int q    = i >> 7;
        float4 v  = ((const float4*)g_v)[nodeBase + node];
        float4 w0 = __ldg(&((const float4*)W1)[0 * 32 + q]);
        float4 w1 = __ldg(&((const float4*)W1)[1 * 32 + q]);
        float4 w2 = __ldg(&((const float4*)W1)[2 * 32 + q]);
        float4 bq = __ldg(&((const float4*)b1)[q]);
        sh1T[(4 * q + 0) * 128 + node] = fmaxf(fmaf(v.x, w0.x, fmaf(v.y, w1.x, fmaf(v.z, w2.x, bq.x))), 0.f);
        sh1T[(4 * q + 1) * 128 + node] = fmaxf(fmaf(v.x, w0.y, fmaf(v.y, w1.y, fmaf(v.z, w2.y, bq.y))), 0.f);
        sh1T[(4 * q + 2) * 128 + node] = fmaxf(fmaf(v.x, w0.z, fmaf(v.y, w1.z, fmaf(v.z, w2.z, bq.z))), 0.f);
        sh1T[(4 * q + 3) * 128 + node] = fmaxf(fmaf(v.x, w0.w, fmaf(v.y, w1.w, fmaf(v.z, w2.w, bq.w))), 0.f);
    }
    __syncthreads();

    int c  = tid & 15;        // cols 4c..4c+3
    int m0 = (tid >> 4) * 8;  // nodes m0..m0+7 (4 packed pairs)

    unsigned long long acc[4][4];
    #pragma unroll
    for (int p = 0; p < 4; p++)
        #pragma unroll
        for (int cc = 0; cc < 4; cc++) acc[p][cc] = 0ull;

    #pragma unroll 2
    for (int kb = 0; kb < HID; kb += 4) {
        #pragma unroll
        for (int kk = 0; kk < 4; kk++) {
            int k = kb + kk;
            float4 w = sW2[k * 16 + c];
            unsigned long long wp[4];
            PACK2(wp[0], w.x, w.x);
            PACK2(wp[1], w.y, w.y);
            PACK2(wp[2], w.z, w.z);
            PACK2(wp[3], w.w, w.w);
            float4 ha = *(const float4*)&sh1T[k * 128 + m0];
            float4 hb = *(const float4*)&sh1T[k * 128 + m0 + 4];
            unsigned long long hp[4];
            PACK2(hp[0], ha.x, ha.y);
            PACK2(hp[1], ha.z, ha.w);
            PACK2(hp[2], hb.x, hb.y);
            PACK2(hp[3], hb.z, hb.w);
            #pragma unroll
            for (int p = 0; p < 4; p++) {
                FMA2(acc[p][0], hp[p], wp[0], acc[p][0]);
                FMA2(acc[p][1], hp[p], wp[1], acc[p][1]);
                FMA2(acc[p][2], hp[p], wp[2], acc[p][2]);
                FMA2(acc[p][3], hp[p], wp[3], acc[p][3]);
            }
        }
    }

    #pragma unroll
    for (int p = 0; p < 4; p++) {
        int n0 = nodeBase + m0 + 2 * p;
        float d0 = g_dinv[n0];
        float d1 = g_dinv[n0 + 1];
        float4 r0, r1;
        UNPACK2(r0.x, r1.x, acc[p][0]);
        UNPACK2(r0.y, r1.y, acc[p][1]);
        UNPACK2(r0.z, r1.z, acc[p][2]);
        UNPACK2(r0.w, r1.w, acc[p][3]);
        r0.x *= d0; r0.y *= d0; r0.z *= d0; r0.w *= d0;
        r1.x *= d1; r1.y *= d1; r1.z *= d1; r1.w *= d1;
        ((float4*)g_h2w)[(size_t)n0 * 16 + c] = r0;
        ((float4*)g_h2w)[(size_t)(n0 + 1) * 16 + c] = r1;
    }
}

// 6) layer-2 gather, 16 threads/node (one float4 quad each), unroll x4.
//    out = dinv[d]*(sum h2w[s] + h2w[d]) + b2. Also resets deg/total.
__global__ void k_gather2(const float* __restrict__ b2,
                          float* __restrict__ out) {
    int gid = blockIdx.x * blockDim.x + threadIdx.x;
    int node = gid >> 4;
    int q    = gid & 15;
    if (node >= N_NODES) return;
    int row = g_rowstart[node];
    int deg = g_deg[node];
    int end = row + deg;
    if (q == 0) g_deg[node] = 0;     // reset for next call (lanes read deg above)
    if (gid == 0) g_total = 0;
    float4 acc = ((const float4*)g_h2w)[(size_t)node * 16 + q];  // self term
    int e = row;
    for (; e + 4 <= end; e += 4) {
        int s0 = g_csrc[e];
        int s1 = g_csrc[e + 1];
        int s2 = g_csrc[e + 2];
        int s3 = g_csrc[e + 3];
        float4 h0 = ((const float4*)g_h2w)[(size_t)s0 * 16 + q];
        float4 h1 = ((const float4*)g_h2w)[(size_t)s1 * 16 + q];
        float4 h2 = ((const float4*)g_h2w)[(size_t)s2 * 16 + q];
        float4 h3 = ((const float4*)g_h2w)[(size_t)s3 * 16 + q];
        acc.x += (h0.x + h1.x) + (h2.x + h3.x);
        acc.y += (h0.y + h1.y) + (h2.y + h3.y);
        acc.z += (h0.z + h1.z) + (h2.z + h3.z);
        acc.w += (h0.w + h1.w) + (h2.w + h3.w);
    }
    for (; e < end; e++) {
        float4 h = ((const float4*)g_h2w)[(size_t)g_csrc[e] * 16 + q];
        acc.x += h.x;
        acc.y += h.y;
        acc.z += h.z;
        acc.w += h.w;
    }
    float dd = g_dinv[node];
    float4 bb = __ldg(&((const float4*)b2)[q]);
    float4 o;
    o.x = fmaf(dd, acc.x, bb.x);
    o.y = fmaf(dd, acc.y, bb.y);
    o.z = fmaf(dd, acc.z, bb.z);
    o.w = fmaf(dd, acc.w, bb.w);
    ((float4*)out)[(size_t)node * 16 + q] = o;
}

extern "C" void kernel_launch(void* const* d_in, const int* in_sizes, int n_in,
                              void* d_out, int out_size) {
    const float* x  = (const float*)d_in[0];
    const int*   ei = (const int*)d_in[1];   // int64 in ref -> int32 on device (JAX x64 off)
    const float* W1 = (const float*)d_in[2];
    const float* b1 = (const float*)d_in[3];
    const float* W2 = (const float*)d_in[4];
    const float* b2 = (const float*)d_in[5];
    float* out = (float*)d_out;

    k_deg<<<(N_EDGES / 2 + 255) / 256, 256>>>(ei);
    k_assign<<<(N_NODES + 255) / 256, 256>>>(x);
    k_csr<<<(N_EDGES / 2 + 255) / 256, 256>>>(ei);
    k_gather1<<<(N_NODES * 8 + 255) / 256, 256>>>();
    k_h2<<<N_PAD / 128, 256>>>(W1, b1, W2);
    k_gather2<<<(N_NODES * 16 + 255) / 256, 256>>>(b2, out);
}